// round 4
// baseline (speedup 1.0000x reference)
#include <cuda_runtime.h>
#include <cuda_bf16.h>
#include <math.h>
#include <limits.h>

// ---------------- problem constants ----------------
#define KSEL   50          // NUM_POINTS
#define FDIM   90          // feature dim
#define PCAP   4096        // PMAX
#define RMAX   256
#define NMAX   600000
#define SMAX   16          // max split-K slices
#define NB     512         // grouping blocks (private histograms)

// weight segment sizes / offsets in the packed split-weight buffer
#define WS1 (4500*256)
#define WS2 (256*256)
#define WS3 (256*512)
#define WS4 (512*256)
#define WS5 (256*512)
#define WO1 0
#define WO2 (WO1+WS1)
#define WO3 (WO2+WS2)
#define WO4 (WO3+WS3)
#define WO5 (WO4+WS4)
#define WTOT (WO5+WS5)

// ---------------- device scratch (no allocs allowed) ----------------
__device__ int      g_counts[RMAX];
__device__ int      g_offsets[RMAX];
__device__ int      g_bc[NB * RMAX];
__device__ int      g_bbase[NB * RMAX];
__device__ float4   g_packed[NMAX];
__device__ float    g_part[SMAX * RMAX * 512];
__device__ unsigned g_whi[WTOT];
__device__ unsigned g_wlo[WTOT];
__device__ unsigned g_xhi0[RMAX * KSEL * FDIM];   // big act split (feat / even layers)
__device__ unsigned g_xlo0[RMAX * KSEL * FDIM];
__device__ unsigned g_xhi1[RMAX * 512];           // small act split (odd layers)
__device__ unsigned g_xlo1[RMAX * 512];

__device__ __forceinline__ void split_tf32(float x, unsigned& hi, unsigned& lo) {
    unsigned h;
    asm("cvt.rna.tf32.f32 %0, %1;" : "=r"(h) : "f"(x));
    float rres = x - __uint_as_float(h);
    unsigned l;
    asm("cvt.rna.tf32.f32 %0, %1;" : "=r"(l) : "f"(rres));
    hi = h; lo = l;
}

// ---------------- weight pre-split (independent of data path) ----------------
__global__ void split_weights_kernel(const float* __restrict__ w1,
                                     const float* __restrict__ w2,
                                     const float* __restrict__ w3,
                                     const float* __restrict__ w4,
                                     const float* __restrict__ w5) {
    for (int i = blockIdx.x * blockDim.x + threadIdx.x; i < WTOT;
         i += gridDim.x * blockDim.x) {
        float v;
        if (i < WO2)      v = w1[i - WO1];
        else if (i < WO3) v = w2[i - WO2];
        else if (i < WO4) v = w3[i - WO3];
        else if (i < WO5) v = w4[i - WO4];
        else              v = w5[i - WO5];
        unsigned h, l;
        split_tf32(v, h, l);
        g_whi[i] = h;
        g_wlo[i] = l;
    }
}

// ---------------- grouping ----------------
__global__ void blockhist_kernel(const int* __restrict__ idx, int Np, int chunk) {
    __shared__ int sh[RMAX];
    int b = blockIdx.x;
    int t = threadIdx.x;
    if (t < RMAX) sh[t] = 0;
    __syncthreads();
    int i0 = b * chunk;
    int i1 = i0 + chunk; if (i1 > Np) i1 = Np;
    for (int i = i0 + t; i < i1; i += blockDim.x)
        atomicAdd(&sh[idx[i]], 1);
    __syncthreads();
    if (t < RMAX) g_bc[b * RMAX + t] = sh[t];
}

__global__ void totals_scan_kernel() {
    __shared__ int tmp[RMAX];
    int r = threadIdx.x;
    int c = 0;
    for (int b = 0; b < NB; b++) c += g_bc[b * RMAX + r];
    g_counts[r] = c;
    tmp[r] = c;
    __syncthreads();
    for (int o = 1; o < RMAX; o <<= 1) {
        int x = (r >= o) ? tmp[r - o] : 0;
        __syncthreads();
        tmp[r] += x;
        __syncthreads();
    }
    g_offsets[r] = tmp[r] - c;
}

__global__ void blockbase_kernel() {
    __shared__ int tmp[NB];
    int r = blockIdx.x;
    int t = threadIdx.x;
    int v = g_bc[t * RMAX + r];
    tmp[t] = v;
    __syncthreads();
    for (int o = 1; o < NB; o <<= 1) {
        int x = (t >= o) ? tmp[t - o] : 0;
        __syncthreads();
        tmp[t] += x;
        __syncthreads();
    }
    g_bbase[t * RMAX + r] = g_offsets[r] + tmp[t] - v;
}

__global__ void scatter_kernel(const int* __restrict__ idx,
                               const float* __restrict__ coords,
                               int Np, int chunk) {
    __shared__ int sc[RMAX];
    int b = blockIdx.x;
    int t = threadIdx.x;
    if (t < RMAX) sc[t] = g_bbase[b * RMAX + t];
    __syncthreads();
    int i0 = b * chunk;
    int i1 = i0 + chunk; if (i1 > Np) i1 = Np;
    for (int i = i0 + t; i < i1; i += blockDim.x) {
        int r = idx[i];
        int slot = atomicAdd(&sc[r], 1);
        float4 p;
        p.x = coords[3 * i + 0];
        p.y = coords[3 * i + 1];
        p.z = coords[3 * i + 2];
        p.w = __int_as_float(i);
        g_packed[slot] = p;
    }
}

// ---------------- FPS (+fused gather+split): one block (512 thr) per ROI -------
// dynamic smem: sx,sy,sz (float[PCAP]) = 48KB
#define FPW 8   // PCAP / 512
__global__ __launch_bounds__(512, 3) void fps_kernel(const float* __restrict__ feats) {
    extern __shared__ float sm[];
    float* sx = sm;
    float* sy = sx + PCAP;
    float* sz = sy + PCAP;

    __shared__ float rv[2][16];
    __shared__ int   rid[2][16], rpos[2][16];
    __shared__ int   ssel[KSEL];

    int r = blockIdx.x;
    int P = g_counts[r];
    if (P > PCAP) P = PCAP;
    int tid = threadIdx.x;
    const size_t rowbase = (size_t)r * (KSEL * FDIM);

    if (P == 0) {
        for (int e = tid; e < KSEL * FDIM; e += 512) {
            g_xhi0[rowbase + e] = 0u;
            g_xlo0[rowbase + e] = 0u;
        }
        return;
    }
    int off = g_offsets[r];

    float rx[FPW], ry[FPW], rz[FPW], rd[FPW];
    int   rgid[FPW];

#pragma unroll
    for (int jj = 0; jj < FPW; jj++) {
        int j = tid + jj * 512;
        if (j < P) {
            float4 p = g_packed[off + j];
            rx[jj] = p.x; ry[jj] = p.y; rz[jj] = p.z;
            rgid[jj] = __float_as_int(p.w);
            sx[j] = p.x; sy[j] = p.y; sz[j] = p.z;
        }
        rd[jj] = 1e10f;
    }

    float lx, ly, lz;

    // first selection: minimum global id (stable position 0)
    {
        int bi = INT_MAX, bp = 0;
#pragma unroll
        for (int jj = 0; jj < FPW; jj++) {
            int j = tid + jj * 512;
            if (j < P && rgid[jj] < bi) { bi = rgid[jj]; bp = j; }
        }
        for (int o = 16; o > 0; o >>= 1) {
            int oi = __shfl_down_sync(~0u, bi, o);
            int op = __shfl_down_sync(~0u, bp, o);
            if (oi < bi) { bi = oi; bp = op; }
        }
        if ((tid & 31) == 0) { rid[0][tid >> 5] = bi; rpos[0][tid >> 5] = bp; }
        __syncthreads();
        int BI = rid[0][0], BP = rpos[0][0];
#pragma unroll
        for (int w = 1; w < 16; w++) {
            int wi = rid[0][w];
            if (wi < BI) { BI = wi; BP = rpos[0][w]; }
        }
        if (tid == 0) ssel[0] = BI;
        lx = sx[BP]; ly = sy[BP]; lz = sz[BP];
    }

    for (int it = 1; it < KSEL; it++) {
        int pb = it & 1;
        float bv = -2.0f; int bi = INT_MAX; int bp = 0;
#pragma unroll
        for (int jj = 0; jj < FPW; jj++) {
            int j = tid + jj * 512;
            if (j < P) {
                float dx = rx[jj] - lx, dy = ry[jj] - ly, dz = rz[jj] - lz;
                float d  = dx * dx + dy * dy + dz * dz;
                float nd = fminf(rd[jj], d);
                rd[jj] = nd;
                if (nd > bv || (nd == bv && rgid[jj] < bi)) { bv = nd; bi = rgid[jj]; bp = j; }
            }
        }
        for (int o = 16; o > 0; o >>= 1) {
            float ov = __shfl_down_sync(~0u, bv, o);
            int   oi = __shfl_down_sync(~0u, bi, o);
            int   op = __shfl_down_sync(~0u, bp, o);
            if (ov > bv || (ov == bv && oi < bi)) { bv = ov; bi = oi; bp = op; }
        }
        if ((tid & 31) == 0) {
            rv[pb][tid >> 5] = bv; rid[pb][tid >> 5] = bi; rpos[pb][tid >> 5] = bp;
        }
        __syncthreads();
        float BV = rv[pb][0]; int BI = rid[pb][0], BP = rpos[pb][0];
#pragma unroll
        for (int w = 1; w < 16; w++) {
            float wv = rv[pb][w]; int wi = rid[pb][w];
            if (wv > BV || (wv == BV && wi < BI)) { BV = wv; BI = wi; BP = rpos[pb][w]; }
        }
        if (tid == 0) ssel[it] = BI;
        lx = sx[BP]; ly = sy[BP]; lz = sz[BP];
    }
    __syncthreads();

    // fused feature gather + tf32 split
    for (int e = tid; e < KSEL * FDIM; e += 512) {
        int k = e / FDIM;
        int f = e - k * FDIM;
        float v = feats[(size_t)ssel[k] * FDIM + f];
        unsigned h, l;
        split_tf32(v, h, l);
        g_xhi0[rowbase + e] = h;
        g_xlo0[rowbase + e] = l;
    }
}

// ---------------- tensor-core split-K GEMM on pre-split tf32 ----------------
#define MMA_TF32(D, A0, A1, A2, A3, B0, B1)                                   \
    asm volatile("mma.sync.aligned.m16n8k8.row.col.f32.tf32.tf32.f32 "        \
                 "{%0,%1,%2,%3},{%4,%5,%6,%7},{%8,%9},{%0,%1,%2,%3};"         \
                 : "+f"(D[0]), "+f"(D[1]), "+f"(D[2]), "+f"(D[3])             \
                 : "r"(A0), "r"(A1), "r"(A2), "r"(A3), "r"(B0), "r"(B1))

__global__ __launch_bounds__(128) void gemm_tc_kernel(const unsigned* __restrict__ Ahi,
                                                      const unsigned* __restrict__ Alo,
                                                      const unsigned* __restrict__ Bhi,
                                                      const unsigned* __restrict__ Blo,
                                                      int M, int N, int K, int chunk) {
    __shared__ unsigned Ashi[64][36], Aslo[64][36];
    __shared__ unsigned Bshi[32][72], Bslo[32][72];
    int s  = blockIdx.z;
    int k0 = s * chunk;
    int k1 = k0 + chunk; if (k1 > K) k1 = K;
    int m0 = blockIdx.y * 64, n0 = blockIdx.x * 64;
    int tid = threadIdx.x;
    int lane = tid & 31, w = tid >> 5;
    int wm = w >> 1, wn = w & 1;
    int g = lane >> 2, q = lane & 3;

    float d[2][4][4];
#pragma unroll
    for (int mi = 0; mi < 2; mi++)
#pragma unroll
        for (int ni = 0; ni < 4; ni++)
#pragma unroll
            for (int e = 0; e < 4; e++) d[mi][ni][e] = 0.0f;

    for (int kb = k0; kb < k1; kb += 32) {
        if (kb + 32 <= k1) {
#pragma unroll
            for (int i = 0; i < 4; i++) {
                int id = tid + i * 128;
                int row = id >> 3, c4 = id & 7;
                size_t src = (size_t)(m0 + row) * K + kb + c4 * 4;
                *(uint4*)&Ashi[row][c4 * 4] = *(const uint4*)&Ahi[src];
                *(uint4*)&Aslo[row][c4 * 4] = *(const uint4*)&Alo[src];
            }
#pragma unroll
            for (int i = 0; i < 4; i++) {
                int id = tid + i * 128;
                int row = id >> 4, c4 = id & 15;
                size_t src = (size_t)(kb + row) * N + n0 + c4 * 4;
                *(uint4*)&Bshi[row][c4 * 4] = *(const uint4*)&Bhi[src];
                *(uint4*)&Bslo[row][c4 * 4] = *(const uint4*)&Blo[src];
            }
        } else {
            for (int i = tid; i < 64 * 32; i += 128) {
                int row = i >> 5, c = i & 31;
                int kg = kb + c;
                size_t src = (size_t)(m0 + row) * K + kg;
                Ashi[row][c] = (kg < k1) ? Ahi[src] : 0u;
                Aslo[row][c] = (kg < k1) ? Alo[src] : 0u;
            }
            for (int i = tid; i < 32 * 64; i += 128) {
                int row = i >> 6, c = i & 63;
                int kg = kb + row;
                size_t src = (size_t)kg * N + n0 + c;
                Bshi[row][c] = (kg < k1) ? Bhi[src] : 0u;
                Bslo[row][c] = (kg < k1) ? Blo[src] : 0u;
            }
        }
        __syncthreads();
#pragma unroll
        for (int k8 = 0; k8 < 32; k8 += 8) {
            unsigned ah[2][4], al[2][4], bh[4][2], bl[4][2];
#pragma unroll
            for (int mi = 0; mi < 2; mi++) {
                int r0 = wm * 32 + mi * 16 + g;
                ah[mi][0] = Ashi[r0][k8 + q];       al[mi][0] = Aslo[r0][k8 + q];
                ah[mi][1] = Ashi[r0 + 8][k8 + q];   al[mi][1] = Aslo[r0 + 8][k8 + q];
                ah[mi][2] = Ashi[r0][k8 + q + 4];   al[mi][2] = Aslo[r0][k8 + q + 4];
                ah[mi][3] = Ashi[r0 + 8][k8 + q + 4]; al[mi][3] = Aslo[r0 + 8][k8 + q + 4];
            }
#pragma unroll
            for (int ni = 0; ni < 4; ni++) {
                int col = wn * 32 + ni * 8 + g;
                bh[ni][0] = Bshi[k8 + q][col];      bl[ni][0] = Bslo[k8 + q][col];
                bh[ni][1] = Bshi[k8 + q + 4][col];  bl[ni][1] = Bslo[k8 + q + 4][col];
            }
#pragma unroll
            for (int mi = 0; mi < 2; mi++)
#pragma unroll
                for (int ni = 0; ni < 4; ni++) {
                    MMA_TF32(d[mi][ni], ah[mi][0], ah[mi][1], ah[mi][2], ah[mi][3],
                             bh[ni][0], bh[ni][1]);
                    MMA_TF32(d[mi][ni], ah[mi][0], ah[mi][1], ah[mi][2], ah[mi][3],
                             bl[ni][0], bl[ni][1]);
                    MMA_TF32(d[mi][ni], al[mi][0], al[mi][1], al[mi][2], al[mi][3],
                             bh[ni][0], bh[ni][1]);
                }
        }
        __syncthreads();
    }

    float* P = g_part + (size_t)s * M * N;
#pragma unroll
    for (int mi = 0; mi < 2; mi++) {
#pragma unroll
        for (int ni = 0; ni < 4; ni++) {
            int m_ = m0 + wm * 32 + mi * 16 + g;
            int n_ = n0 + wn * 32 + ni * 8 + q * 2;
            *(float2*)&P[(size_t)m_ * N + n_]       = make_float2(d[mi][ni][0], d[mi][ni][1]);
            *(float2*)&P[(size_t)(m_ + 8) * N + n_] = make_float2(d[mi][ni][2], d[mi][ni][3]);
        }
    }
}

// ---------------- combine split-K + bias + BN(train) + ReLU + split epilogue ---
__global__ __launch_bounds__(256) void bn_combine_kernel(const float* __restrict__ bias,
                                                         const float* __restrict__ gam,
                                                         const float* __restrict__ bet,
                                                         float* __restrict__ outRaw,
                                                         unsigned* __restrict__ outHi,
                                                         unsigned* __restrict__ outLo,
                                                         int M, int N, int S, int relu) {
    __shared__ float red[256];
    __shared__ float cmean[8], cvar[8];
    int t = threadIdx.x;
    int n0 = blockIdx.x * 8;
    int col = n0 + (t & 7);
    int mrow = t >> 3;

    float bn = bias[col];
    float v[8];
    float psum = 0.0f;
#pragma unroll
    for (int j = 0; j < 8; j++) {
        int m = mrow + 32 * j;
        float acc = bn;
        for (int s = 0; s < S; s++)
            acc += g_part[(size_t)s * M * N + (size_t)m * N + col];
        v[j] = acc;
        psum += acc;
    }
    red[t] = psum;
    __syncthreads();
    for (int st = 128; st >= 8; st >>= 1) {
        if (t < st) red[t] += red[t + st];
        __syncthreads();
    }
    if (t < 8) cmean[t] = red[t] / (float)M;
    __syncthreads();
    float mean = cmean[t & 7];

    float pss = 0.0f;
#pragma unroll
    for (int j = 0; j < 8; j++) {
        float dd = v[j] - mean;
        pss += dd * dd;
    }
    red[t] = pss;
    __syncthreads();
    for (int st = 128; st >= 8; st >>= 1) {
        if (t < st) red[t] += red[t + st];
        __syncthreads();
    }
    if (t < 8) cvar[t] = red[t] / (float)M;
    __syncthreads();
    float inv = rsqrtf(cvar[t & 7] + 1e-5f);
    float gm = gam[col], bt = bet[col];

#pragma unroll
    for (int j = 0; j < 8; j++) {
        int m = mrow + 32 * j;
        float y = gm * (v[j] - mean) * inv + bt;
        if (relu) y = fmaxf(y, 0.0f);
        size_t o = (size_t)m * N + col;
        if (outRaw) outRaw[o] = y;
        if (outHi) {
            unsigned h, l;
            split_tf32(y, h, l);
            outHi[o] = h;
            outLo[o] = l;
        }
    }
}

// ---------------- host ----------------
static void run_layer(const unsigned* Ahi, const unsigned* Alo,
                      const unsigned* Bhi, const unsigned* Blo,
                      const float* b, const float* g, const float* be,
                      float* yRaw, unsigned* yHi, unsigned* yLo,
                      int M, int K, int N, int S, int relu) {
    int chunk = ((K + S - 1) / S + 31) & ~31;
    dim3 grid(N / 64, M / 64, S);
    gemm_tc_kernel<<<grid, 128>>>(Ahi, Alo, Bhi, Blo, M, N, K, chunk);
    bn_combine_kernel<<<N / 8, 256>>>(b, g, be, yRaw, yHi, yLo, M, N, S, relu);
}

extern "C" void kernel_launch(void* const* d_in, const int* in_sizes, int n_in,
                              void* d_out, int out_size) {
    const int*   roi_idx = (const int*)d_in[1];
    const float* feats   = (const float*)d_in[2];
    const float* coords  = (const float*)d_in[3];
    const float* w1 = (const float*)d_in[4],  *b1 = (const float*)d_in[5];
    const float* g1 = (const float*)d_in[6],  *be1 = (const float*)d_in[7];
    const float* w2 = (const float*)d_in[8],  *b2 = (const float*)d_in[9];
    const float* g2 = (const float*)d_in[10], *be2 = (const float*)d_in[11];
    const float* w3 = (const float*)d_in[12], *b3 = (const float*)d_in[13];
    const float* g3 = (const float*)d_in[14], *be3 = (const float*)d_in[15];
    const float* w4 = (const float*)d_in[16], *b4 = (const float*)d_in[17];
    const float* g4 = (const float*)d_in[18], *be4 = (const float*)d_in[19];
    const float* w5 = (const float*)d_in[20], *b5 = (const float*)d_in[21];
    const float* g5 = (const float*)d_in[22], *be5 = (const float*)d_in[23];

    int R  = out_size / 512;
    int Np = in_sizes[1];
    float* out = (float*)d_out;

    unsigned *whi_p, *wlo_p, *xhi0_p, *xlo0_p, *xhi1_p, *xlo1_p;
    cudaGetSymbolAddress((void**)&whi_p,  g_whi);
    cudaGetSymbolAddress((void**)&wlo_p,  g_wlo);
    cudaGetSymbolAddress((void**)&xhi0_p, g_xhi0);
    cudaGetSymbolAddress((void**)&xlo0_p, g_xlo0);
    cudaGetSymbolAddress((void**)&xhi1_p, g_xhi1);
    cudaGetSymbolAddress((void**)&xlo1_p, g_xlo1);

    const int FPS_SMEM = PCAP * 3 * (int)sizeof(float);  // 48KB
    cudaFuncSetAttribute(fps_kernel, cudaFuncAttributeMaxDynamicSharedMemorySize, FPS_SMEM);

    // weights split (independent)
    split_weights_kernel<<<592, 512>>>(w1, w2, w3, w4, w5);

    // grouping
    int chunk = (Np + NB - 1) / NB;
    blockhist_kernel<<<NB, 512>>>(roi_idx, Np, chunk);
    totals_scan_kernel<<<1, 256>>>();
    blockbase_kernel<<<RMAX, NB>>>();
    scatter_kernel<<<NB, 512>>>(roi_idx, coords, Np, chunk);

    // FPS + fused gather/split
    fps_kernel<<<R, 512, FPS_SMEM>>>(feats);

    // MLP (3xTF32 tensor-core GEMMs on pre-split inputs)
    run_layer(xhi0_p, xlo0_p, whi_p + WO1, wlo_p + WO1, b1, g1, be1,
              nullptr, xhi1_p, xlo1_p, R, KSEL * FDIM, 256, 12, 1);
    run_layer(xhi1_p, xlo1_p, whi_p + WO2, wlo_p + WO2, b2, g2, be2,
              nullptr, xhi0_p, xlo0_p, R, 256, 256, 4, 1);
    run_layer(xhi0_p, xlo0_p, whi_p + WO3, wlo_p + WO3, b3, g3, be3,
              nullptr, xhi1_p, xlo1_p, R, 256, 512, 4, 0);
    run_layer(xhi1_p, xlo1_p, whi_p + WO4, wlo_p + WO4, b4, g4, be4,
              nullptr, xhi0_p, xlo0_p, R, 512, 256, 4, 1);
    run_layer(xhi0_p, xlo0_p, whi_p + WO5, wlo_p + WO5, b5, g5, be5,
              out, nullptr, nullptr, R, 256, 512, 4, 1);
}

// round 5
// speedup vs baseline: 1.0325x; 1.0325x over previous
#include <cuda_runtime.h>
#include <cuda_bf16.h>
#include <math.h>
#include <limits.h>

// ---------------- problem constants ----------------
#define KSEL   50          // NUM_POINTS
#define FDIM   90          // feature dim
#define PCAP   4096        // PMAX
#define RMAX   256
#define NMAX   600000
#define SMAX   16          // max split-K slices
#define NB     240         // grouping blocks (private histograms)

// weight segment offsets in the packed split-weight buffer
#define WS1 (4500*256)
#define WS2 (256*256)
#define WS3 (256*512)
#define WS4 (512*256)
#define WS5 (256*512)
#define WO1 0
#define WO2 (WO1+WS1)
#define WO3 (WO2+WS2)
#define WO4 (WO3+WS3)
#define WO5 (WO4+WS4)
#define WTOT (WO5+WS5)

// ---------------- device scratch (no allocs allowed) ----------------
__device__ int      g_counts[RMAX];
__device__ int      g_offsets[RMAX];
__device__ int      g_bc[NB * RMAX];
__device__ int      g_bbase[NB * RMAX];
__device__ float4   g_packed[NMAX];
__device__ float    g_feat[RMAX * KSEL * FDIM];
__device__ float    g_part[SMAX * RMAX * 512];
__device__ float    g_hA[RMAX * 512];
__device__ float    g_hB[RMAX * 512];
__device__ unsigned g_whi[WTOT];
__device__ unsigned g_wlo[WTOT];

__device__ __forceinline__ void split_tf32(float x, unsigned& hi, unsigned& lo) {
    unsigned h;
    asm("cvt.rna.tf32.f32 %0, %1;" : "=r"(h) : "f"(x));
    float rres = x - __uint_as_float(h);
    unsigned l;
    asm("cvt.rna.tf32.f32 %0, %1;" : "=r"(l) : "f"(rres));
    hi = h; lo = l;
}

// ---------------- weight pre-split ----------------
__global__ void split_weights_kernel(const float* __restrict__ w1,
                                     const float* __restrict__ w2,
                                     const float* __restrict__ w3,
                                     const float* __restrict__ w4,
                                     const float* __restrict__ w5) {
    for (int i = blockIdx.x * blockDim.x + threadIdx.x; i < WTOT;
         i += gridDim.x * blockDim.x) {
        float v;
        if (i < WO2)      v = w1[i - WO1];
        else if (i < WO3) v = w2[i - WO2];
        else if (i < WO4) v = w3[i - WO3];
        else if (i < WO5) v = w4[i - WO4];
        else              v = w5[i - WO5];
        unsigned h, l;
        split_tf32(v, h, l);
        g_whi[i] = h;
        g_wlo[i] = l;
    }
}

// ---------------- grouping ----------------
__global__ void blockhist_kernel(const int* __restrict__ idx, int Np, int chunk) {
    __shared__ int sh[RMAX];
    int b = blockIdx.x;
    int t = threadIdx.x;
    if (t < RMAX) sh[t] = 0;
    __syncthreads();
    int i0 = b * chunk;
    int i1 = i0 + chunk; if (i1 > Np) i1 = Np;
    for (int i = i0 + t; i < i1; i += blockDim.x)
        atomicAdd(&sh[idx[i]], 1);
    __syncthreads();
    if (t < RMAX) g_bc[b * RMAX + t] = sh[t];
}

__global__ void totals_scan_kernel() {
    __shared__ int tmp[RMAX];
    int r = threadIdx.x;
    int c = 0;
    for (int b = 0; b < NB; b++) c += g_bc[b * RMAX + r];
    g_counts[r] = c;
    tmp[r] = c;
    __syncthreads();
    for (int o = 1; o < RMAX; o <<= 1) {
        int x = (r >= o) ? tmp[r - o] : 0;
        __syncthreads();
        tmp[r] += x;
        __syncthreads();
    }
    g_offsets[r] = tmp[r] - c;
}

__global__ void blockbase_kernel() {
    __shared__ int tmp[256];
    int r = blockIdx.x;
    int t = threadIdx.x;
    int v = (t < NB) ? g_bc[t * RMAX + r] : 0;
    tmp[t] = v;
    __syncthreads();
    for (int o = 1; o < 256; o <<= 1) {
        int x = (t >= o) ? tmp[t - o] : 0;
        __syncthreads();
        tmp[t] += x;
        __syncthreads();
    }
    if (t < NB) g_bbase[t * RMAX + r] = g_offsets[r] + tmp[t] - v;
}

__global__ void scatter_kernel(const int* __restrict__ idx,
                               const float* __restrict__ coords,
                               int Np, int chunk) {
    __shared__ int sc[RMAX];
    int b = blockIdx.x;
    int t = threadIdx.x;
    if (t < RMAX) sc[t] = g_bbase[b * RMAX + t];
    __syncthreads();
    int i0 = b * chunk;
    int i1 = i0 + chunk; if (i1 > Np) i1 = Np;
    for (int i = i0 + t; i < i1; i += blockDim.x) {
        int r = idx[i];
        int slot = atomicAdd(&sc[r], 1);
        float4 p;
        p.x = coords[3 * i + 0];
        p.y = coords[3 * i + 1];
        p.z = coords[3 * i + 2];
        p.w = __int_as_float(i);
        g_packed[slot] = p;
    }
}

// ---------------- FPS (+fused gather): one block (512 thr) per ROI -------
// dynamic smem: sx,sy,sz (float[PCAP]) = 48KB; single barrier per iteration
#define FPW 8   // PCAP / 512
__global__ __launch_bounds__(512, 3) void fps_kernel(const float* __restrict__ feats) {
    extern __shared__ float sm[];
    float* sx = sm;
    float* sy = sx + PCAP;
    float* sz = sy + PCAP;

    __shared__ float rv[2][16];
    __shared__ int   rid[2][16], rpos[2][16];
    __shared__ int   ssel[KSEL];

    int r = blockIdx.x;
    int P = g_counts[r];
    if (P > PCAP) P = PCAP;
    int tid = threadIdx.x;
    const size_t rowbase = (size_t)r * (KSEL * FDIM);

    if (P == 0) {
        for (int e = tid; e < KSEL * FDIM; e += 512)
            g_feat[rowbase + e] = 0.0f;
        return;
    }
    int off = g_offsets[r];

    float rx[FPW], ry[FPW], rz[FPW], rd[FPW];
    int   rgid[FPW];

#pragma unroll
    for (int jj = 0; jj < FPW; jj++) {
        int j = tid + jj * 512;
        if (j < P) {
            float4 p = g_packed[off + j];
            rx[jj] = p.x; ry[jj] = p.y; rz[jj] = p.z;
            rgid[jj] = __float_as_int(p.w);
            sx[j] = p.x; sy[j] = p.y; sz[j] = p.z;
        }
        rd[jj] = 1e10f;
    }

    float lx, ly, lz;

    // first selection: minimum global id (stable position 0)
    {
        int bi = INT_MAX, bp = 0;
#pragma unroll
        for (int jj = 0; jj < FPW; jj++) {
            int j = tid + jj * 512;
            if (j < P && rgid[jj] < bi) { bi = rgid[jj]; bp = j; }
        }
        for (int o = 16; o > 0; o >>= 1) {
            int oi = __shfl_down_sync(~0u, bi, o);
            int op = __shfl_down_sync(~0u, bp, o);
            if (oi < bi) { bi = oi; bp = op; }
        }
        if ((tid & 31) == 0) { rid[0][tid >> 5] = bi; rpos[0][tid >> 5] = bp; }
        __syncthreads();
        int BI = rid[0][0], BP = rpos[0][0];
#pragma unroll
        for (int w = 1; w < 16; w++) {
            int wi = rid[0][w];
            if (wi < BI) { BI = wi; BP = rpos[0][w]; }
        }
        if (tid == 0) ssel[0] = BI;
        lx = sx[BP]; ly = sy[BP]; lz = sz[BP];
    }

    for (int it = 1; it < KSEL; it++) {
        int pb = it & 1;
        float bv = -2.0f; int bi = INT_MAX; int bp = 0;
#pragma unroll
        for (int jj = 0; jj < FPW; jj++) {
            int j = tid + jj * 512;
            if (j < P) {
                float dx = rx[jj] - lx, dy = ry[jj] - ly, dz = rz[jj] - lz;
                float d  = dx * dx + dy * dy + dz * dz;
                float nd = fminf(rd[jj], d);
                rd[jj] = nd;
                if (nd > bv || (nd == bv && rgid[jj] < bi)) { bv = nd; bi = rgid[jj]; bp = j; }
            }
        }
        for (int o = 16; o > 0; o >>= 1) {
            float ov = __shfl_down_sync(~0u, bv, o);
            int   oi = __shfl_down_sync(~0u, bi, o);
            int   op = __shfl_down_sync(~0u, bp, o);
            if (ov > bv || (ov == bv && oi < bi)) { bv = ov; bi = oi; bp = op; }
        }
        if ((tid & 31) == 0) {
            rv[pb][tid >> 5] = bv; rid[pb][tid >> 5] = bi; rpos[pb][tid >> 5] = bp;
        }
        __syncthreads();
        float BV = rv[pb][0]; int BI = rid[pb][0], BP = rpos[pb][0];
#pragma unroll
        for (int w = 1; w < 16; w++) {
            float wv = rv[pb][w]; int wi = rid[pb][w];
            if (wv > BV || (wv == BV && wi < BI)) { BV = wv; BI = wi; BP = rpos[pb][w]; }
        }
        if (tid == 0) ssel[it] = BI;
        lx = sx[BP]; ly = sy[BP]; lz = sz[BP];
    }
    __syncthreads();

    // fused feature gather
    for (int e = tid; e < KSEL * FDIM; e += 512) {
        int k = e / FDIM;
        int f = e - k * FDIM;
        g_feat[rowbase + e] = feats[(size_t)ssel[k] * FDIM + f];
    }
}

// ---------------- tensor-core split-K GEMM (A raw fp32, B pre-split tf32) -----
#define MMA_TF32(D, A0, A1, A2, A3, B0, B1)                                   \
    asm volatile("mma.sync.aligned.m16n8k8.row.col.f32.tf32.tf32.f32 "        \
                 "{%0,%1,%2,%3},{%4,%5,%6,%7},{%8,%9},{%0,%1,%2,%3};"         \
                 : "+f"(D[0]), "+f"(D[1]), "+f"(D[2]), "+f"(D[3])             \
                 : "r"(A0), "r"(A1), "r"(A2), "r"(A3), "r"(B0), "r"(B1))

__global__ __launch_bounds__(128) void gemm_tc_kernel(const float* __restrict__ A,
                                                      const unsigned* __restrict__ Bhi,
                                                      const unsigned* __restrict__ Blo,
                                                      int M, int N, int K, int chunk) {
    __shared__ float    As[64][36];
    __shared__ unsigned Bshi[32][72], Bslo[32][72];
    int s  = blockIdx.z;
    int k0 = s * chunk;
    int k1 = k0 + chunk; if (k1 > K) k1 = K;
    int m0 = blockIdx.y * 64, n0 = blockIdx.x * 64;
    int tid = threadIdx.x;
    int lane = tid & 31, w = tid >> 5;
    int wm = w >> 1, wn = w & 1;
    int g = lane >> 2, q = lane & 3;

    float d[2][4][4];
#pragma unroll
    for (int mi = 0; mi < 2; mi++)
#pragma unroll
        for (int ni = 0; ni < 4; ni++)
#pragma unroll
            for (int e = 0; e < 4; e++) d[mi][ni][e] = 0.0f;

    for (int kb = k0; kb < k1; kb += 32) {
        if (kb + 32 <= k1) {
#pragma unroll
            for (int i = 0; i < 4; i++) {
                int id = tid + i * 128;
                int row = id >> 3, c4 = id & 7;
                float4 v = *(const float4*)&A[(size_t)(m0 + row) * K + kb + c4 * 4];
                *(float4*)&As[row][c4 * 4] = v;
            }
#pragma unroll
            for (int i = 0; i < 4; i++) {
                int id = tid + i * 128;
                int row = id >> 4, c4 = id & 15;
                size_t src = (size_t)(kb + row) * N + n0 + c4 * 4;
                *(uint4*)&Bshi[row][c4 * 4] = *(const uint4*)&Bhi[src];
                *(uint4*)&Bslo[row][c4 * 4] = *(const uint4*)&Blo[src];
            }
        } else {
            for (int i = tid; i < 64 * 32; i += 128) {
                int row = i >> 5, c = i & 31;
                int kg = kb + c;
                As[row][c] = (kg < k1) ? A[(size_t)(m0 + row) * K + kg] : 0.0f;
            }
            for (int i = tid; i < 32 * 64; i += 128) {
                int row = i >> 6, c = i & 63;
                int kg = kb + row;
                size_t src = (size_t)kg * N + n0 + c;
                Bshi[row][c] = (kg < k1) ? Bhi[src] : 0u;
                Bslo[row][c] = (kg < k1) ? Blo[src] : 0u;
            }
        }
        __syncthreads();
#pragma unroll
        for (int k8 = 0; k8 < 32; k8 += 8) {
            unsigned ah[2][4], al[2][4], bh[4][2], bl[4][2];
#pragma unroll
            for (int mi = 0; mi < 2; mi++) {
                int r0 = wm * 32 + mi * 16 + g;
                split_tf32(As[r0][k8 + q],           ah[mi][0], al[mi][0]);
                split_tf32(As[r0 + 8][k8 + q],       ah[mi][1], al[mi][1]);
                split_tf32(As[r0][k8 + q + 4],       ah[mi][2], al[mi][2]);
                split_tf32(As[r0 + 8][k8 + q + 4],   ah[mi][3], al[mi][3]);
            }
#pragma unroll
            for (int ni = 0; ni < 4; ni++) {
                int col = wn * 32 + ni * 8 + g;
                bh[ni][0] = Bshi[k8 + q][col];      bl[ni][0] = Bslo[k8 + q][col];
                bh[ni][1] = Bshi[k8 + q + 4][col];  bl[ni][1] = Bslo[k8 + q + 4][col];
            }
#pragma unroll
            for (int mi = 0; mi < 2; mi++)
#pragma unroll
                for (int ni = 0; ni < 4; ni++) {
                    MMA_TF32(d[mi][ni], ah[mi][0], ah[mi][1], ah[mi][2], ah[mi][3],
                             bh[ni][0], bh[ni][1]);
                    MMA_TF32(d[mi][ni], ah[mi][0], ah[mi][1], ah[mi][2], ah[mi][3],
                             bl[ni][0], bl[ni][1]);
                    MMA_TF32(d[mi][ni], al[mi][0], al[mi][1], al[mi][2], al[mi][3],
                             bh[ni][0], bh[ni][1]);
                }
        }
        __syncthreads();
    }

    float* P = g_part + (size_t)s * M * N;
#pragma unroll
    for (int mi = 0; mi < 2; mi++) {
#pragma unroll
        for (int ni = 0; ni < 4; ni++) {
            int m_ = m0 + wm * 32 + mi * 16 + g;
            int n_ = n0 + wn * 32 + ni * 8 + q * 2;
            *(float2*)&P[(size_t)m_ * N + n_]       = make_float2(d[mi][ni][0], d[mi][ni][1]);
            *(float2*)&P[(size_t)(m_ + 8) * N + n_] = make_float2(d[mi][ni][2], d[mi][ni][3]);
        }
    }
}

// ---------------- combine split-K + bias + BatchNorm(train) + optional ReLU ----
__global__ __launch_bounds__(256) void bn_combine_kernel(const float* __restrict__ bias,
                                                         const float* __restrict__ gam,
                                                         const float* __restrict__ bet,
                                                         float* __restrict__ out,
                                                         int M, int N, int S, int relu) {
    __shared__ float red[256];
    __shared__ float cmean[8], cvar[8];
    int t = threadIdx.x;
    int n0 = blockIdx.x * 8;
    int col = n0 + (t & 7);
    int mrow = t >> 3;

    float bn = bias[col];
    float v[8];
    float psum = 0.0f;
#pragma unroll
    for (int j = 0; j < 8; j++) {
        int m = mrow + 32 * j;
        float acc = bn;
        for (int s = 0; s < S; s++)
            acc += g_part[(size_t)s * M * N + (size_t)m * N + col];
        v[j] = acc;
        psum += acc;
    }
    red[t] = psum;
    __syncthreads();
    for (int st = 128; st >= 8; st >>= 1) {
        if (t < st) red[t] += red[t + st];
        __syncthreads();
    }
    if (t < 8) cmean[t] = red[t] / (float)M;
    __syncthreads();
    float mean = cmean[t & 7];

    float pss = 0.0f;
#pragma unroll
    for (int j = 0; j < 8; j++) {
        float dd = v[j] - mean;
        pss += dd * dd;
    }
    red[t] = pss;
    __syncthreads();
    for (int st = 128; st >= 8; st >>= 1) {
        if (t < st) red[t] += red[t + st];
        __syncthreads();
    }
    if (t < 8) cvar[t] = red[t] / (float)M;
    __syncthreads();
    float inv = rsqrtf(cvar[t & 7] + 1e-5f);
    float gm = gam[col], bt = bet[col];

#pragma unroll
    for (int j = 0; j < 8; j++) {
        int m = mrow + 32 * j;
        float y = gm * (v[j] - mean) * inv + bt;
        if (relu) y = fmaxf(y, 0.0f);
        out[(size_t)m * N + col] = y;
    }
}

// ---------------- host ----------------
static void run_layer(const float* X, const unsigned* Bhi, const unsigned* Blo,
                      const float* b, const float* g, const float* be, float* Y,
                      int M, int K, int N, int S, int relu) {
    int chunk = ((K + S - 1) / S + 31) & ~31;
    dim3 grid(N / 64, M / 64, S);
    gemm_tc_kernel<<<grid, 128>>>(X, Bhi, Blo, M, N, K, chunk);
    bn_combine_kernel<<<N / 8, 256>>>(b, g, be, Y, M, N, S, relu);
}

extern "C" void kernel_launch(void* const* d_in, const int* in_sizes, int n_in,
                              void* d_out, int out_size) {
    const int*   roi_idx = (const int*)d_in[1];
    const float* feats   = (const float*)d_in[2];
    const float* coords  = (const float*)d_in[3];
    const float* w1 = (const float*)d_in[4],  *b1 = (const float*)d_in[5];
    const float* g1 = (const float*)d_in[6],  *be1 = (const float*)d_in[7];
    const float* w2 = (const float*)d_in[8],  *b2 = (const float*)d_in[9];
    const float* g2 = (const float*)d_in[10], *be2 = (const float*)d_in[11];
    const float* w3 = (const float*)d_in[12], *b3 = (const float*)d_in[13];
    const float* g3 = (const float*)d_in[14], *be3 = (const float*)d_in[15];
    const float* w4 = (const float*)d_in[16], *b4 = (const float*)d_in[17];
    const float* g4 = (const float*)d_in[18], *be4 = (const float*)d_in[19];
    const float* w5 = (const float*)d_in[20], *b5 = (const float*)d_in[21];
    const float* g5 = (const float*)d_in[22], *be5 = (const float*)d_in[23];

    int R  = out_size / 512;
    int Np = in_sizes[1];
    float* out = (float*)d_out;

    float *feat_p, *hA_p, *hB_p;
    unsigned *whi_p, *wlo_p;
    cudaGetSymbolAddress((void**)&feat_p, g_feat);
    cudaGetSymbolAddress((void**)&hA_p,  g_hA);
    cudaGetSymbolAddress((void**)&hB_p,  g_hB);
    cudaGetSymbolAddress((void**)&whi_p, g_whi);
    cudaGetSymbolAddress((void**)&wlo_p, g_wlo);

    const int FPS_SMEM = PCAP * 3 * (int)sizeof(float);  // 48KB
    cudaFuncSetAttribute(fps_kernel, cudaFuncAttributeMaxDynamicSharedMemorySize, FPS_SMEM);

    // weights split (amortized: read once per launch)
    split_weights_kernel<<<592, 512>>>(w1, w2, w3, w4, w5);

    // grouping (privatized, no global atomics)
    int chunk = (Np + NB - 1) / NB;
    blockhist_kernel<<<NB, 512>>>(roi_idx, Np, chunk);
    totals_scan_kernel<<<1, 256>>>();
    blockbase_kernel<<<RMAX, 256>>>();
    scatter_kernel<<<NB, 512>>>(roi_idx, coords, Np, chunk);

    // FPS + fused gather
    fps_kernel<<<R, 512, FPS_SMEM>>>(feats);

    // MLP (3xTF32 tensor-core GEMMs; A split in-loop, W pre-split)
    run_layer(feat_p, whi_p + WO1, wlo_p + WO1, b1, g1, be1, hA_p, R, KSEL * FDIM, 256, 8, 1);
    run_layer(hA_p,   whi_p + WO2, wlo_p + WO2, b2, g2, be2, hB_p, R, 256,          256, 4, 1);
    run_layer(hB_p,   whi_p + WO3, wlo_p + WO3, b3, g3, be3, hA_p, R, 256,          512, 4, 0);
    run_layer(hA_p,   whi_p + WO4, wlo_p + WO4, b4, g4, be4, hB_p, R, 512,          256, 4, 1);
    run_layer(hB_p,   whi_p + WO5, wlo_p + WO5, b5, g5, be5, out,  R, 256,          512, 4, 1);
}

// round 6
// speedup vs baseline: 1.1702x; 1.1334x over previous
#include <cuda_runtime.h>
#include <cuda_bf16.h>
#include <math.h>
#include <limits.h>

// ---------------- problem constants ----------------
#define KSEL   50          // NUM_POINTS
#define FDIM   90          // feature dim
#define PCAP   4096        // PMAX
#define RMAX   256
#define NMAX   600000
#define SMAX   16          // max split-K slices
#define NB     240         // grouping blocks (private histograms)

// ---------------- device scratch (no allocs allowed) ----------------
__device__ int    g_counts[RMAX];
__device__ int    g_offsets[RMAX];
__device__ int    g_bc[NB * RMAX];
__device__ int    g_bbase[NB * RMAX];
__device__ float4 g_packed[NMAX];
__device__ float  g_feat[RMAX * KSEL * FDIM];
__device__ float  g_part[SMAX * RMAX * 512];
__device__ float  g_hA[RMAX * 512];
__device__ float  g_hB[RMAX * 512];

// ---------------- grouping ----------------
__global__ void blockhist_kernel(const int* __restrict__ idx, int Np, int chunk) {
    __shared__ int sh[RMAX];
    int b = blockIdx.x;
    int t = threadIdx.x;
    if (t < RMAX) sh[t] = 0;
    __syncthreads();
    int i0 = b * chunk;
    int i1 = i0 + chunk; if (i1 > Np) i1 = Np;
    for (int i = i0 + t; i < i1; i += blockDim.x)
        atomicAdd(&sh[idx[i]], 1);
    __syncthreads();
    if (t < RMAX) g_bc[b * RMAX + t] = sh[t];
}

__global__ void totals_scan_kernel() {
    __shared__ int wsum[8];
    int r = threadIdx.x;
    int c = 0;
    for (int b = 0; b < NB; b++) c += g_bc[b * RMAX + r];
    g_counts[r] = c;
    // inclusive scan over 256 via warp shfl
    int v = c;
    for (int o = 1; o < 32; o <<= 1) {
        int x = __shfl_up_sync(~0u, v, o);
        if ((r & 31) >= o) v += x;
    }
    if ((r & 31) == 31) wsum[r >> 5] = v;
    __syncthreads();
    if (r < 8) {
        int s = wsum[r];
        for (int o = 1; o < 8; o <<= 1) {
            int x = __shfl_up_sync(0xff, s, o);
            if (r >= o) s += x;
        }
        wsum[r] = s;
    }
    __syncthreads();
    int pre = (r >= 32) ? wsum[(r >> 5) - 1] : 0;
    g_offsets[r] = pre + v - c;   // exclusive
}

__global__ void blockbase_kernel() {
    __shared__ int wsum[8];
    int r = blockIdx.x;
    int t = threadIdx.x;
    int c = (t < NB) ? g_bc[t * RMAX + r] : 0;
    int v = c;
    for (int o = 1; o < 32; o <<= 1) {
        int x = __shfl_up_sync(~0u, v, o);
        if ((t & 31) >= o) v += x;
    }
    if ((t & 31) == 31) wsum[t >> 5] = v;
    __syncthreads();
    if (t < 8) {
        int s = wsum[t];
        for (int o = 1; o < 8; o <<= 1) {
            int x = __shfl_up_sync(0xff, s, o);
            if (t >= o) s += x;
        }
        wsum[t] = s;
    }
    __syncthreads();
    int pre = (t >= 32) ? wsum[(t >> 5) - 1] : 0;
    if (t < NB) g_bbase[t * RMAX + r] = g_offsets[r] + pre + v - c;
}

__global__ void scatter_kernel(const int* __restrict__ idx,
                               const float* __restrict__ coords,
                               int Np, int chunk) {
    __shared__ int sc[RMAX];
    int b = blockIdx.x;
    int t = threadIdx.x;
    if (t < RMAX) sc[t] = g_bbase[b * RMAX + t];
    __syncthreads();
    int i0 = b * chunk;
    int i1 = i0 + chunk; if (i1 > Np) i1 = Np;
    for (int i = i0 + t; i < i1; i += blockDim.x) {
        int r = idx[i];
        int slot = atomicAdd(&sc[r], 1);
        float4 p;
        p.x = coords[3 * i + 0];
        p.y = coords[3 * i + 1];
        p.z = coords[3 * i + 2];
        p.w = __int_as_float(i);
        g_packed[slot] = p;
    }
}

// ---------------- FPS (+fused gather): one block (512 thr) per ROI -------
// dynamic smem: sx,sy,sz (float[PCAP]) = 48KB; single barrier per iteration
// NOTE: __launch_bounds__(512, 2) — occ 2 keeps regs <= 64, no spills
#define FPW 8   // PCAP / 512
__global__ __launch_bounds__(512, 2) void fps_kernel(const float* __restrict__ feats) {
    extern __shared__ float sm[];
    float* sx = sm;
    float* sy = sx + PCAP;
    float* sz = sy + PCAP;

    __shared__ float rv[2][16];
    __shared__ int   rid[2][16], rpos[2][16];
    __shared__ int   ssel[KSEL];

    int r = blockIdx.x;
    int P = g_counts[r];
    if (P > PCAP) P = PCAP;
    int tid = threadIdx.x;
    const size_t rowbase = (size_t)r * (KSEL * FDIM);

    if (P == 0) {
        for (int e = tid; e < KSEL * FDIM; e += 512)
            g_feat[rowbase + e] = 0.0f;
        return;
    }
    int off = g_offsets[r];

    float rx[FPW], ry[FPW], rz[FPW], rd[FPW];
    int   rgid[FPW];

#pragma unroll
    for (int jj = 0; jj < FPW; jj++) {
        int j = tid + jj * 512;
        if (j < P) {
            float4 p = g_packed[off + j];
            rx[jj] = p.x; ry[jj] = p.y; rz[jj] = p.z;
            rgid[jj] = __float_as_int(p.w);
            sx[j] = p.x; sy[j] = p.y; sz[j] = p.z;
        }
        rd[jj] = 1e10f;
    }

    float lx, ly, lz;

    // first selection: minimum global id (stable position 0)
    {
        int bi = INT_MAX, bp = 0;
#pragma unroll
        for (int jj = 0; jj < FPW; jj++) {
            int j = tid + jj * 512;
            if (j < P && rgid[jj] < bi) { bi = rgid[jj]; bp = j; }
        }
        for (int o = 16; o > 0; o >>= 1) {
            int oi = __shfl_down_sync(~0u, bi, o);
            int op = __shfl_down_sync(~0u, bp, o);
            if (oi < bi) { bi = oi; bp = op; }
        }
        if ((tid & 31) == 0) { rid[0][tid >> 5] = bi; rpos[0][tid >> 5] = bp; }
        __syncthreads();
        int BI = rid[0][0], BP = rpos[0][0];
#pragma unroll
        for (int w = 1; w < 16; w++) {
            int wi = rid[0][w];
            if (wi < BI) { BI = wi; BP = rpos[0][w]; }
        }
        if (tid == 0) ssel[0] = BI;
        lx = sx[BP]; ly = sy[BP]; lz = sz[BP];
    }

    for (int it = 1; it < KSEL; it++) {
        int pb = it & 1;
        float bv = -2.0f; int bi = INT_MAX; int bp = 0;
#pragma unroll
        for (int jj = 0; jj < FPW; jj++) {
            int j = tid + jj * 512;
            if (j < P) {
                float dx = rx[jj] - lx, dy = ry[jj] - ly, dz = rz[jj] - lz;
                float d  = dx * dx + dy * dy + dz * dz;
                float nd = fminf(rd[jj], d);
                rd[jj] = nd;
                if (nd > bv || (nd == bv && rgid[jj] < bi)) { bv = nd; bi = rgid[jj]; bp = j; }
            }
        }
        for (int o = 16; o > 0; o >>= 1) {
            float ov = __shfl_down_sync(~0u, bv, o);
            int   oi = __shfl_down_sync(~0u, bi, o);
            int   op = __shfl_down_sync(~0u, bp, o);
            if (ov > bv || (ov == bv && oi < bi)) { bv = ov; bi = oi; bp = op; }
        }
        if ((tid & 31) == 0) {
            rv[pb][tid >> 5] = bv; rid[pb][tid >> 5] = bi; rpos[pb][tid >> 5] = bp;
        }
        __syncthreads();
        float BV = rv[pb][0]; int BI = rid[pb][0], BP = rpos[pb][0];
#pragma unroll
        for (int w = 1; w < 16; w++) {
            float wv = rv[pb][w]; int wi = rid[pb][w];
            if (wv > BV || (wv == BV && wi < BI)) { BV = wv; BI = wi; BP = rpos[pb][w]; }
        }
        if (tid == 0) ssel[it] = BI;
        lx = sx[BP]; ly = sy[BP]; lz = sz[BP];
    }
    __syncthreads();

    // fused feature gather
    for (int e = tid; e < KSEL * FDIM; e += 512) {
        int k = e / FDIM;
        int f = e - k * FDIM;
        g_feat[rowbase + e] = feats[(size_t)ssel[k] * FDIM + f];
    }
}

// ---------------- tensor-core split-K GEMM (3xTF32, in-loop split) ------------
__device__ __forceinline__ void split_tf32(float x, unsigned& hi, unsigned& lo) {
    unsigned h;
    asm("cvt.rna.tf32.f32 %0, %1;" : "=r"(h) : "f"(x));
    float rres = x - __uint_as_float(h);
    unsigned l;
    asm("cvt.rna.tf32.f32 %0, %1;" : "=r"(l) : "f"(rres));
    hi = h; lo = l;
}

#define MMA_TF32(D, A0, A1, A2, A3, B0, B1)                                   \
    asm volatile("mma.sync.aligned.m16n8k8.row.col.f32.tf32.tf32.f32 "        \
                 "{%0,%1,%2,%3},{%4,%5,%6,%7},{%8,%9},{%0,%1,%2,%3};"         \
                 : "+f"(D[0]), "+f"(D[1]), "+f"(D[2]), "+f"(D[3])             \
                 : "r"(A0), "r"(A1), "r"(A2), "r"(A3), "r"(B0), "r"(B1))

__global__ __launch_bounds__(128) void gemm_tc_kernel(const float* __restrict__ A,
                                                      const float* __restrict__ B,
                                                      int M, int N, int K, int chunk) {
    __shared__ float As[64][36];
    __shared__ float Bs[32][72];
    int s  = blockIdx.z;
    int k0 = s * chunk;
    int k1 = k0 + chunk; if (k1 > K) k1 = K;
    int m0 = blockIdx.y * 64, n0 = blockIdx.x * 64;
    int tid = threadIdx.x;
    int lane = tid & 31, w = tid >> 5;
    int wm = w >> 1, wn = w & 1;
    int g = lane >> 2, q = lane & 3;

    float d[2][4][4];
#pragma unroll
    for (int mi = 0; mi < 2; mi++)
#pragma unroll
        for (int ni = 0; ni < 4; ni++)
#pragma unroll
            for (int e = 0; e < 4; e++) d[mi][ni][e] = 0.0f;

    for (int kb = k0; kb < k1; kb += 32) {
        if (kb + 32 <= k1) {
#pragma unroll
            for (int i = 0; i < 4; i++) {
                int id = tid + i * 128;
                int row = id >> 3, c4 = id & 7;
                float4 v = *(const float4*)&A[(size_t)(m0 + row) * K + kb + c4 * 4];
                *(float4*)&As[row][c4 * 4] = v;
            }
#pragma unroll
            for (int i = 0; i < 4; i++) {
                int id = tid + i * 128;
                int row = id >> 4, c4 = id & 15;
                float4 v = *(const float4*)&B[(size_t)(kb + row) * N + n0 + c4 * 4];
                *(float4*)&Bs[row][c4 * 4] = v;
            }
        } else {
            for (int i = tid; i < 64 * 32; i += 128) {
                int row = i >> 5, c = i & 31;
                int kg = kb + c;
                As[row][c] = (kg < k1) ? A[(size_t)(m0 + row) * K + kg] : 0.0f;
            }
            for (int i = tid; i < 32 * 64; i += 128) {
                int row = i >> 6, c = i & 63;
                int kg = kb + row;
                Bs[row][c] = (kg < k1) ? B[(size_t)kg * N + n0 + c] : 0.0f;
            }
        }
        __syncthreads();
#pragma unroll
        for (int k8 = 0; k8 < 32; k8 += 8) {
            unsigned ah[2][4], al[2][4], bh[4][2], bl[4][2];
#pragma unroll
            for (int mi = 0; mi < 2; mi++) {
                int r0 = wm * 32 + mi * 16 + g;
                split_tf32(As[r0][k8 + q],         ah[mi][0], al[mi][0]);
                split_tf32(As[r0 + 8][k8 + q],     ah[mi][1], al[mi][1]);
                split_tf32(As[r0][k8 + q + 4],     ah[mi][2], al[mi][2]);
                split_tf32(As[r0 + 8][k8 + q + 4], ah[mi][3], al[mi][3]);
            }
#pragma unroll
            for (int ni = 0; ni < 4; ni++) {
                int col = wn * 32 + ni * 8 + g;
                split_tf32(Bs[k8 + q][col],     bh[ni][0], bl[ni][0]);
                split_tf32(Bs[k8 + q + 4][col], bh[ni][1], bl[ni][1]);
            }
#pragma unroll
            for (int mi = 0; mi < 2; mi++)
#pragma unroll
                for (int ni = 0; ni < 4; ni++) {
                    MMA_TF32(d[mi][ni], ah[mi][0], ah[mi][1], ah[mi][2], ah[mi][3],
                             bh[ni][0], bh[ni][1]);
                    MMA_TF32(d[mi][ni], ah[mi][0], ah[mi][1], ah[mi][2], ah[mi][3],
                             bl[ni][0], bl[ni][1]);
                    MMA_TF32(d[mi][ni], al[mi][0], al[mi][1], al[mi][2], al[mi][3],
                             bh[ni][0], bh[ni][1]);
                }
        }
        __syncthreads();
    }

    float* P = g_part + (size_t)s * M * N;
#pragma unroll
    for (int mi = 0; mi < 2; mi++) {
#pragma unroll
        for (int ni = 0; ni < 4; ni++) {
            int m_ = m0 + wm * 32 + mi * 16 + g;
            int n_ = n0 + wn * 32 + ni * 8 + q * 2;
            *(float2*)&P[(size_t)m_ * N + n_]       = make_float2(d[mi][ni][0], d[mi][ni][1]);
            *(float2*)&P[(size_t)(m_ + 8) * N + n_] = make_float2(d[mi][ni][2], d[mi][ni][3]);
        }
    }
}

// ---------------- combine split-K + bias + BatchNorm(train) + optional ReLU ----
__global__ __launch_bounds__(256) void bn_combine_kernel(const float* __restrict__ bias,
                                                         const float* __restrict__ gam,
                                                         const float* __restrict__ bet,
                                                         float* __restrict__ out,
                                                         int M, int N, int S, int relu) {
    __shared__ float red[256];
    __shared__ float cmean[8], cvar[8];
    int t = threadIdx.x;
    int n0 = blockIdx.x * 8;
    int col = n0 + (t & 7);
    int mrow = t >> 3;

    float bn = bias[col];
    float v[8];
    float psum = 0.0f;
#pragma unroll
    for (int j = 0; j < 8; j++) {
        int m = mrow + 32 * j;
        float acc = bn;
        for (int s = 0; s < S; s++)
            acc += g_part[(size_t)s * M * N + (size_t)m * N + col];
        v[j] = acc;
        psum += acc;
    }
    red[t] = psum;
    __syncthreads();
    for (int st = 128; st >= 8; st >>= 1) {
        if (t < st) red[t] += red[t + st];
        __syncthreads();
    }
    if (t < 8) cmean[t] = red[t] / (float)M;
    __syncthreads();
    float mean = cmean[t & 7];

    float pss = 0.0f;
#pragma unroll
    for (int j = 0; j < 8; j++) {
        float dd = v[j] - mean;
        pss += dd * dd;
    }
    red[t] = pss;
    __syncthreads();
    for (int st = 128; st >= 8; st >>= 1) {
        if (t < st) red[t] += red[t + st];
        __syncthreads();
    }
    if (t < 8) cvar[t] = red[t] / (float)M;
    __syncthreads();
    float inv = rsqrtf(cvar[t & 7] + 1e-5f);
    float gm = gam[col], bt = bet[col];

#pragma unroll
    for (int j = 0; j < 8; j++) {
        int m = mrow + 32 * j;
        float y = gm * (v[j] - mean) * inv + bt;
        if (relu) y = fmaxf(y, 0.0f);
        out[(size_t)m * N + col] = y;
    }
}

// ---------------- host ----------------
static void run_layer(const float* X, const float* W, const float* b,
                      const float* g, const float* be, float* Y,
                      int M, int K, int N, int S, int relu) {
    int chunk = ((K + S - 1) / S + 31) & ~31;
    dim3 grid(N / 64, M / 64, S);
    gemm_tc_kernel<<<grid, 128>>>(X, W, M, N, K, chunk);
    bn_combine_kernel<<<N / 8, 256>>>(b, g, be, Y, M, N, S, relu);
}

extern "C" void kernel_launch(void* const* d_in, const int* in_sizes, int n_in,
                              void* d_out, int out_size) {
    const int*   roi_idx = (const int*)d_in[1];
    const float* feats   = (const float*)d_in[2];
    const float* coords  = (const float*)d_in[3];
    const float* w1 = (const float*)d_in[4],  *b1 = (const float*)d_in[5];
    const float* g1 = (const float*)d_in[6],  *be1 = (const float*)d_in[7];
    const float* w2 = (const float*)d_in[8],  *b2 = (const float*)d_in[9];
    const float* g2 = (const float*)d_in[10], *be2 = (const float*)d_in[11];
    const float* w3 = (const float*)d_in[12], *b3 = (const float*)d_in[13];
    const float* g3 = (const float*)d_in[14], *be3 = (const float*)d_in[15];
    const float* w4 = (const float*)d_in[16], *b4 = (const float*)d_in[17];
    const float* g4 = (const float*)d_in[18], *be4 = (const float*)d_in[19];
    const float* w5 = (const float*)d_in[20], *b5 = (const float*)d_in[21];
    const float* g5 = (const float*)d_in[22], *be5 = (const float*)d_in[23];

    int R  = out_size / 512;
    int Np = in_sizes[1];
    float* out = (float*)d_out;

    float *feat_p, *hA_p, *hB_p;
    cudaGetSymbolAddress((void**)&feat_p, g_feat);
    cudaGetSymbolAddress((void**)&hA_p,  g_hA);
    cudaGetSymbolAddress((void**)&hB_p,  g_hB);

    const int FPS_SMEM = PCAP * 3 * (int)sizeof(float);  // 48KB
    cudaFuncSetAttribute(fps_kernel, cudaFuncAttributeMaxDynamicSharedMemorySize, FPS_SMEM);

    // grouping (privatized, no global atomics)
    int chunk = (Np + NB - 1) / NB;
    blockhist_kernel<<<NB, 512>>>(roi_idx, Np, chunk);
    totals_scan_kernel<<<1, 256>>>();
    blockbase_kernel<<<RMAX, 256>>>();
    scatter_kernel<<<NB, 512>>>(roi_idx, coords, Np, chunk);

    // FPS + fused gather
    fps_kernel<<<R, 512, FPS_SMEM>>>(feats);

    // MLP (3xTF32 tensor-core GEMMs)
    run_layer(feat_p, w1, b1, g1, be1, hA_p, R, KSEL * FDIM, 256, 8, 1);
    run_layer(hA_p,   w2, b2, g2, be2, hB_p, R, 256,          256, 4, 1);
    run_layer(hB_p,   w3, b3, g3, be3, hA_p, R, 256,          512, 4, 0);
    run_layer(hA_p,   w4, b4, g4, be4, hB_p, R, 512,          256, 4, 1);
    run_layer(hB_p,   w5, b5, g5, be5, out,  R, 256,          512, 4, 1);
}

// round 7
// speedup vs baseline: 1.2427x; 1.0619x over previous
#include <cuda_runtime.h>
#include <cuda_bf16.h>
#include <math.h>
#include <limits.h>

// ---------------- problem constants ----------------
#define KSEL   50          // NUM_POINTS
#define FDIM   90          // feature dim
#define PCAP   4096        // PMAX
#define RMAX   256
#define NMAX   600000
#define SMAX   16          // max split-K slices
#define NB     240         // grouping blocks (private histograms)

// ---------------- device scratch (no allocs allowed) ----------------
__device__ int    g_counts[RMAX];
__device__ int    g_offsets[RMAX];
__device__ int    g_bc[NB * RMAX];
__device__ int    g_bbase[NB * RMAX];
__device__ float4 g_packed[NMAX];
__device__ float  g_feat[RMAX * KSEL * FDIM];
__device__ float  g_part[SMAX * RMAX * 512];
__device__ float  g_hA[RMAX * 512];
__device__ float  g_hB[RMAX * 512];

// ---------------- grouping ----------------
__global__ void blockhist_kernel(const int* __restrict__ idx, int Np, int chunk) {
    __shared__ int sh[RMAX];
    int b = blockIdx.x;
    int t = threadIdx.x;
    if (t < RMAX) sh[t] = 0;
    __syncthreads();
    int i0 = b * chunk;
    int i1 = i0 + chunk; if (i1 > Np) i1 = Np;
    for (int i = i0 + t; i < i1; i += blockDim.x)
        atomicAdd(&sh[idx[i]], 1);
    __syncthreads();
    if (t < RMAX) g_bc[b * RMAX + t] = sh[t];
}

__global__ void totals_scan_kernel() {
    __shared__ int wsum[8];
    int r = threadIdx.x;
    int c = 0;
    for (int b = 0; b < NB; b++) c += g_bc[b * RMAX + r];
    g_counts[r] = c;
    int v = c;
    for (int o = 1; o < 32; o <<= 1) {
        int x = __shfl_up_sync(~0u, v, o);
        if ((r & 31) >= o) v += x;
    }
    if ((r & 31) == 31) wsum[r >> 5] = v;
    __syncthreads();
    if (r < 8) {
        int s = wsum[r];
        for (int o = 1; o < 8; o <<= 1) {
            int x = __shfl_up_sync(0xff, s, o);
            if (r >= o) s += x;
        }
        wsum[r] = s;
    }
    __syncthreads();
    int pre = (r >= 32) ? wsum[(r >> 5) - 1] : 0;
    g_offsets[r] = pre + v - c;   // exclusive
}

__global__ void blockbase_kernel() {
    __shared__ int wsum[8];
    int r = blockIdx.x;
    int t = threadIdx.x;
    int c = (t < NB) ? g_bc[t * RMAX + r] : 0;
    int v = c;
    for (int o = 1; o < 32; o <<= 1) {
        int x = __shfl_up_sync(~0u, v, o);
        if ((t & 31) >= o) v += x;
    }
    if ((t & 31) == 31) wsum[t >> 5] = v;
    __syncthreads();
    if (t < 8) {
        int s = wsum[t];
        for (int o = 1; o < 8; o <<= 1) {
            int x = __shfl_up_sync(0xff, s, o);
            if (t >= o) s += x;
        }
        wsum[t] = s;
    }
    __syncthreads();
    int pre = (t >= 32) ? wsum[(t >> 5) - 1] : 0;
    if (t < NB) g_bbase[t * RMAX + r] = g_offsets[r] + pre + v - c;
}

__global__ void scatter_kernel(const int* __restrict__ idx,
                               const float* __restrict__ coords,
                               int Np, int chunk) {
    __shared__ int sc[RMAX];
    int b = blockIdx.x;
    int t = threadIdx.x;
    if (t < RMAX) sc[t] = g_bbase[b * RMAX + t];
    __syncthreads();
    int i0 = b * chunk;
    int i1 = i0 + chunk; if (i1 > Np) i1 = Np;
    for (int i = i0 + t; i < i1; i += blockDim.x) {
        int r = idx[i];
        int slot = atomicAdd(&sc[r], 1);
        float4 p;
        p.x = coords[3 * i + 0];
        p.y = coords[3 * i + 1];
        p.z = coords[3 * i + 2];
        p.w = __int_as_float(i);
        g_packed[slot] = p;
    }
}

// ---------------- FPS (+fused gather): one block (512 thr) per ROI -------
// One barrier per iteration; post-barrier reduce is a lane-parallel butterfly
// (3 LDS + 15 SHFL per warp, winner broadcast to all lanes).
#define FPW 8   // PCAP / 512
__global__ __launch_bounds__(512, 2) void fps_kernel(const float* __restrict__ feats) {
    extern __shared__ float sm[];
    float* sx = sm;
    float* sy = sx + PCAP;
    float* sz = sy + PCAP;

    __shared__ float rv[2][16];
    __shared__ int   rid[2][16], rpos[2][16];
    __shared__ int   ssel[KSEL];

    int r = blockIdx.x;
    int P = g_counts[r];
    if (P > PCAP) P = PCAP;
    int tid = threadIdx.x;
    int lane = tid & 31;
    const size_t rowbase = (size_t)r * (KSEL * FDIM);

    if (P == 0) {
        for (int e = tid; e < KSEL * FDIM; e += 512)
            g_feat[rowbase + e] = 0.0f;
        return;
    }
    int off = g_offsets[r];

    float rx[FPW], ry[FPW], rz[FPW], rd[FPW];
    int   rgid[FPW];

#pragma unroll
    for (int jj = 0; jj < FPW; jj++) {
        int j = tid + jj * 512;
        if (j < P) {
            float4 p = g_packed[off + j];
            rx[jj] = p.x; ry[jj] = p.y; rz[jj] = p.z;
            rgid[jj] = __float_as_int(p.w);
            sx[j] = p.x; sy[j] = p.y; sz[j] = p.z;
        }
        rd[jj] = 1e10f;
    }

    float lx, ly, lz;

    // first selection: minimum global id (stable position 0)
    {
        int bi = INT_MAX, bp = 0;
#pragma unroll
        for (int jj = 0; jj < FPW; jj++) {
            int j = tid + jj * 512;
            if (j < P && rgid[jj] < bi) { bi = rgid[jj]; bp = j; }
        }
        for (int o = 16; o > 0; o >>= 1) {
            int oi = __shfl_down_sync(~0u, bi, o);
            int op = __shfl_down_sync(~0u, bp, o);
            if (oi < bi) { bi = oi; bp = op; }
        }
        if (lane == 0) { rid[0][tid >> 5] = bi; rpos[0][tid >> 5] = bp; }
        __syncthreads();
        // lane-parallel butterfly over 16 candidates (all lanes converge)
        int ci = (lane < 16) ? rid[0][lane]  : INT_MAX;
        int cp = (lane < 16) ? rpos[0][lane] : 0;
#pragma unroll
        for (int o = 16; o > 0; o >>= 1) {
            int oi = __shfl_xor_sync(~0u, ci, o);
            int op = __shfl_xor_sync(~0u, cp, o);
            if (oi < ci) { ci = oi; cp = op; }
        }
        if (tid == 0) ssel[0] = ci;
        lx = sx[cp]; ly = sy[cp]; lz = sz[cp];
    }

    for (int it = 1; it < KSEL; it++) {
        int pb = it & 1;
        float bv = -2.0f; int bi = INT_MAX; int bp = 0;
#pragma unroll
        for (int jj = 0; jj < FPW; jj++) {
            int j = tid + jj * 512;
            if (j < P) {
                float dx = rx[jj] - lx, dy = ry[jj] - ly, dz = rz[jj] - lz;
                float d  = dx * dx + dy * dy + dz * dz;
                float nd = fminf(rd[jj], d);
                rd[jj] = nd;
                if (nd > bv || (nd == bv && rgid[jj] < bi)) { bv = nd; bi = rgid[jj]; bp = j; }
            }
        }
        for (int o = 16; o > 0; o >>= 1) {
            float ov = __shfl_down_sync(~0u, bv, o);
            int   oi = __shfl_down_sync(~0u, bi, o);
            int   op = __shfl_down_sync(~0u, bp, o);
            if (ov > bv || (ov == bv && oi < bi)) { bv = ov; bi = oi; bp = op; }
        }
        if (lane == 0) {
            rv[pb][tid >> 5] = bv; rid[pb][tid >> 5] = bi; rpos[pb][tid >> 5] = bp;
        }
        __syncthreads();
        // lane-parallel butterfly over the 16 warp candidates
        float cv = (lane < 16) ? rv[pb][lane]   : -3.0f;
        int   ci = (lane < 16) ? rid[pb][lane]  : INT_MAX;
        int   cp = (lane < 16) ? rpos[pb][lane] : 0;
#pragma unroll
        for (int o = 16; o > 0; o >>= 1) {
            float ov = __shfl_xor_sync(~0u, cv, o);
            int   oi = __shfl_xor_sync(~0u, ci, o);
            int   op = __shfl_xor_sync(~0u, cp, o);
            if (ov > cv || (ov == cv && oi < ci)) { cv = ov; ci = oi; cp = op; }
        }
        if (tid == 0) ssel[it] = ci;
        lx = sx[cp]; ly = sy[cp]; lz = sz[cp];
    }
    __syncthreads();

    // fused feature gather
    for (int e = tid; e < KSEL * FDIM; e += 512) {
        int k = e / FDIM;
        int f = e - k * FDIM;
        g_feat[rowbase + e] = feats[(size_t)ssel[k] * FDIM + f];
    }
}

// ---------------- tensor-core split-K GEMM (3xTF32, in-loop split) ------------
__device__ __forceinline__ void split_tf32(float x, unsigned& hi, unsigned& lo) {
    unsigned h;
    asm("cvt.rna.tf32.f32 %0, %1;" : "=r"(h) : "f"(x));
    float rres = x - __uint_as_float(h);
    unsigned l;
    asm("cvt.rna.tf32.f32 %0, %1;" : "=r"(l) : "f"(rres));
    hi = h; lo = l;
}

#define MMA_TF32(D, A0, A1, A2, A3, B0, B1)                                   \
    asm volatile("mma.sync.aligned.m16n8k8.row.col.f32.tf32.tf32.f32 "        \
                 "{%0,%1,%2,%3},{%4,%5,%6,%7},{%8,%9},{%0,%1,%2,%3};"         \
                 : "+f"(D[0]), "+f"(D[1]), "+f"(D[2]), "+f"(D[3])             \
                 : "r"(A0), "r"(A1), "r"(A2), "r"(A3), "r"(B0), "r"(B1))

__global__ __launch_bounds__(128) void gemm_tc_kernel(const float* __restrict__ A,
                                                      const float* __restrict__ B,
                                                      int M, int N, int K, int chunk) {
    __shared__ float As[64][36];
    __shared__ float Bs[32][72];
    int s  = blockIdx.z;
    int k0 = s * chunk;
    int k1 = k0 + chunk; if (k1 > K) k1 = K;
    int m0 = blockIdx.y * 64, n0 = blockIdx.x * 64;
    int tid = threadIdx.x;
    int lane = tid & 31, w = tid >> 5;
    int wm = w >> 1, wn = w & 1;
    int g = lane >> 2, q = lane & 3;

    float d[2][4][4];
#pragma unroll
    for (int mi = 0; mi < 2; mi++)
#pragma unroll
        for (int ni = 0; ni < 4; ni++)
#pragma unroll
            for (int e = 0; e < 4; e++) d[mi][ni][e] = 0.0f;

    for (int kb = k0; kb < k1; kb += 32) {
        if (kb + 32 <= k1) {
#pragma unroll
            for (int i = 0; i < 4; i++) {
                int id = tid + i * 128;
                int row = id >> 3, c4 = id & 7;
                float4 v = *(const float4*)&A[(size_t)(m0 + row) * K + kb + c4 * 4];
                *(float4*)&As[row][c4 * 4] = v;
            }
#pragma unroll
            for (int i = 0; i < 4; i++) {
                int id = tid + i * 128;
                int row = id >> 4, c4 = id & 15;
                float4 v = *(const float4*)&B[(size_t)(kb + row) * N + n0 + c4 * 4];
                *(float4*)&Bs[row][c4 * 4] = v;
            }
        } else {
            for (int i = tid; i < 64 * 32; i += 128) {
                int row = i >> 5, c = i & 31;
                int kg = kb + c;
                As[row][c] = (kg < k1) ? A[(size_t)(m0 + row) * K + kg] : 0.0f;
            }
            for (int i = tid; i < 32 * 64; i += 128) {
                int row = i >> 6, c = i & 63;
                int kg = kb + row;
                Bs[row][c] = (kg < k1) ? B[(size_t)kg * N + n0 + c] : 0.0f;
            }
        }
        __syncthreads();
#pragma unroll
        for (int k8 = 0; k8 < 32; k8 += 8) {
            unsigned ah[2][4], al[2][4], bh[4][2], bl[4][2];
#pragma unroll
            for (int mi = 0; mi < 2; mi++) {
                int r0 = wm * 32 + mi * 16 + g;
                split_tf32(As[r0][k8 + q],         ah[mi][0], al[mi][0]);
                split_tf32(As[r0 + 8][k8 + q],     ah[mi][1], al[mi][1]);
                split_tf32(As[r0][k8 + q + 4],     ah[mi][2], al[mi][2]);
                split_tf32(As[r0 + 8][k8 + q + 4], ah[mi][3], al[mi][3]);
            }
#pragma unroll
            for (int ni = 0; ni < 4; ni++) {
                int col = wn * 32 + ni * 8 + g;
                split_tf32(Bs[k8 + q][col],     bh[ni][0], bl[ni][0]);
                split_tf32(Bs[k8 + q + 4][col], bh[ni][1], bl[ni][1]);
            }
#pragma unroll
            for (int mi = 0; mi < 2; mi++)
#pragma unroll
                for (int ni = 0; ni < 4; ni++) {
                    MMA_TF32(d[mi][ni], ah[mi][0], ah[mi][1], ah[mi][2], ah[mi][3],
                             bh[ni][0], bh[ni][1]);
                    MMA_TF32(d[mi][ni], ah[mi][0], ah[mi][1], ah[mi][2], ah[mi][3],
                             bl[ni][0], bl[ni][1]);
                    MMA_TF32(d[mi][ni], al[mi][0], al[mi][1], al[mi][2], al[mi][3],
                             bh[ni][0], bh[ni][1]);
                }
        }
        __syncthreads();
    }

    float* P = g_part + (size_t)s * M * N;
#pragma unroll
    for (int mi = 0; mi < 2; mi++) {
#pragma unroll
        for (int ni = 0; ni < 4; ni++) {
            int m_ = m0 + wm * 32 + mi * 16 + g;
            int n_ = n0 + wn * 32 + ni * 8 + q * 2;
            *(float2*)&P[(size_t)m_ * N + n_]       = make_float2(d[mi][ni][0], d[mi][ni][1]);
            *(float2*)&P[(size_t)(m_ + 8) * N + n_] = make_float2(d[mi][ni][2], d[mi][ni][3]);
        }
    }
}

// ---------------- combine split-K + bias + BatchNorm(train) + optional ReLU ----
__global__ __launch_bounds__(256) void bn_combine_kernel(const float* __restrict__ bias,
                                                         const float* __restrict__ gam,
                                                         const float* __restrict__ bet,
                                                         float* __restrict__ out,
                                                         int M, int N, int S, int relu) {
    __shared__ float red[256];
    __shared__ float cmean[8], cvar[8];
    int t = threadIdx.x;
    int n0 = blockIdx.x * 8;
    int col = n0 + (t & 7);
    int mrow = t >> 3;

    float bn = bias[col];
    float v[8];
    float psum = 0.0f;
#pragma unroll
    for (int j = 0; j < 8; j++) {
        int m = mrow + 32 * j;
        float acc = bn;
        for (int s = 0; s < S; s++)
            acc += g_part[(size_t)s * M * N + (size_t)m * N + col];
        v[j] = acc;
        psum += acc;
    }
    red[t] = psum;
    __syncthreads();
    for (int st = 128; st >= 8; st >>= 1) {
        if (t < st) red[t] += red[t + st];
        __syncthreads();
    }
    if (t < 8) cmean[t] = red[t] / (float)M;
    __syncthreads();
    float mean = cmean[t & 7];

    float pss = 0.0f;
#pragma unroll
    for (int j = 0; j < 8; j++) {
        float dd = v[j] - mean;
        pss += dd * dd;
    }
    red[t] = pss;
    __syncthreads();
    for (int st = 128; st >= 8; st >>= 1) {
        if (t < st) red[t] += red[t + st];
        __syncthreads();
    }
    if (t < 8) cvar[t] = red[t] / (float)M;
    __syncthreads();
    float inv = rsqrtf(cvar[t & 7] + 1e-5f);
    float gm = gam[col], bt = bet[col];

#pragma unroll
    for (int j = 0; j < 8; j++) {
        int m = mrow + 32 * j;
        float y = gm * (v[j] - mean) * inv + bt;
        if (relu) y = fmaxf(y, 0.0f);
        out[(size_t)m * N + col] = y;
    }
}

// ---------------- host ----------------
static void run_layer(const float* X, const float* W, const float* b,
                      const float* g, const float* be, float* Y,
                      int M, int K, int N, int S, int relu) {
    int chunk = ((K + S - 1) / S + 31) & ~31;
    dim3 grid(N / 64, M / 64, S);
    gemm_tc_kernel<<<grid, 128>>>(X, W, M, N, K, chunk);
    bn_combine_kernel<<<N / 8, 256>>>(b, g, be, Y, M, N, S, relu);
}

extern "C" void kernel_launch(void* const* d_in, const int* in_sizes, int n_in,
                              void* d_out, int out_size) {
    const int*   roi_idx = (const int*)d_in[1];
    const float* feats   = (const float*)d_in[2];
    const float* coords  = (const float*)d_in[3];
    const float* w1 = (const float*)d_in[4],  *b1 = (const float*)d_in[5];
    const float* g1 = (const float*)d_in[6],  *be1 = (const float*)d_in[7];
    const float* w2 = (const float*)d_in[8],  *b2 = (const float*)d_in[9];
    const float* g2 = (const float*)d_in[10], *be2 = (const float*)d_in[11];
    const float* w3 = (const float*)d_in[12], *b3 = (const float*)d_in[13];
    const float* g3 = (const float*)d_in[14], *be3 = (const float*)d_in[15];
    const float* w4 = (const float*)d_in[16], *b4 = (const float*)d_in[17];
    const float* g4 = (const float*)d_in[18], *be4 = (const float*)d_in[19];
    const float* w5 = (const float*)d_in[20], *b5 = (const float*)d_in[21];
    const float* g5 = (const float*)d_in[22], *be5 = (const float*)d_in[23];

    int R  = out_size / 512;
    int Np = in_sizes[1];
    float* out = (float*)d_out;

    float *feat_p, *hA_p, *hB_p;
    cudaGetSymbolAddress((void**)&feat_p, g_feat);
    cudaGetSymbolAddress((void**)&hA_p,  g_hA);
    cudaGetSymbolAddress((void**)&hB_p,  g_hB);

    const int FPS_SMEM = PCAP * 3 * (int)sizeof(float);  // 48KB
    cudaFuncSetAttribute(fps_kernel, cudaFuncAttributeMaxDynamicSharedMemorySize, FPS_SMEM);

    // grouping (privatized, no global atomics)
    int chunk = (Np + NB - 1) / NB;
    blockhist_kernel<<<NB, 512>>>(roi_idx, Np, chunk);
    totals_scan_kernel<<<1, 256>>>();
    blockbase_kernel<<<RMAX, 256>>>();
    scatter_kernel<<<NB, 512>>>(roi_idx, coords, Np, chunk);

    // FPS + fused gather
    fps_kernel<<<R, 512, FPS_SMEM>>>(feats);

    // MLP (3xTF32 tensor-core GEMMs)
    run_layer(feat_p, w1, b1, g1, be1, hA_p, R, KSEL * FDIM, 256, 8, 1);
    run_layer(hA_p,   w2, b2, g2, be2, hB_p, R, 256,          256, 4, 1);
    run_layer(hB_p,   w3, b3, g3, be3, hA_p, R, 256,          512, 4, 0);
    run_layer(hA_p,   w4, b4, g4, be4, hB_p, R, 512,          256, 4, 1);
    run_layer(hB_p,   w5, b5, g5, be5, out,  R, 256,          512, 4, 1);
}